// round 9
// baseline (speedup 1.0000x reference)
#include <cuda_runtime.h>

#define DD   6
#define KK   16
#define CIN  13
#define NL   3
#define NCP  7        // channel pairs (14 padded channels)
#define WPC  20       // u64 weights per (layer, channel-pair): bias,6 bw,7 nw,6 w2
#define PACK_N (NL * NCP * WPC)        // 420 u64
#define MISC_N 27                      // 54 floats (b2,gw,gb) as 27 u64
#define ALL_N  (PACK_N + MISC_N)

typedef unsigned long long u64;

__device__ __forceinline__ u64 pk2(float lo, float hi) {
    u64 r;
    asm("mov.b64 %0, {%1, %2};" : "=l"(r) : "f"(lo), "f"(hi));
    return r;
}
__device__ __forceinline__ float2 upk2(u64 v) {
    float2 f;
    asm("mov.b64 {%0, %1}, %2;" : "=f"(f.x), "=f"(f.y) : "l"(v));
    return f;
}
__device__ __forceinline__ u64 fma2(u64 a, u64 b, u64 c) {
    u64 r;
    asm("fma.rn.f32x2 %0, %1, %2, %3;" : "=l"(r) : "l"(a), "l"(b), "l"(c));
    return r;
}
__device__ __forceinline__ u64 add2(u64 a, u64 b) {
    u64 r;
    asm("add.rn.f32x2 %0, %1, %2;" : "=l"(r) : "l"(a), "l"(b));
    return r;
}
__device__ __forceinline__ u64 mul2(u64 a, u64 b) {
    u64 r;
    asm("mul.rn.f32x2 %0, %1, %2;" : "=l"(r) : "l"(a), "l"(b));
    return r;
}

#define ABS2(x) ((x) & 0x7FFFFFFF7FFFFFFFull)

// Packed weight row per (l, cp), 20 u64 contiguous:
//   s0      : (b1[c0],  b1[c1])
//   s1..s6  : (W1[q][c0], W1[q][c1])        q = 0..5  (point-emb rows)
//   s7..s13 : (W1[6+i][c0], W1[6+i][c1])    i = 0..6  (neighbor rows)
//   s14..s19: (W2[c0][d], W2[c1][d])        d = 0..5
// c0 = 2cp, c1 = 2cp+1 (c1==13 -> zero pad)
// Appended at [PACK_N..): 54 floats = b2[18], gw[18], gb[18] as 27 u64.
__device__ __align__(16) u64 gStage[ALL_N];
__constant__ __align__(16) u64 cAll[ALL_N];

__global__ void pack_weights_kernel(const float* __restrict__ W1, const float* __restrict__ b1,
                                    const float* __restrict__ W2, const float* __restrict__ b2,
                                    const float* __restrict__ gw, const float* __restrict__ gb)
{
    for (int t = threadIdx.x; t < PACK_N; t += blockDim.x) {
        int l  = t / (NCP * WPC);
        int r  = t % (NCP * WPC);
        int cp = r / WPC;
        int s  = r % WPC;
        int c0 = 2 * cp, c1 = 2 * cp + 1;
        bool ok1 = (c1 < CIN);
        float lo, hi;
        if (s == 0) {
            lo = b1[l * CIN + c0];
            hi = ok1 ? b1[l * CIN + c1] : 0.f;
        } else if (s < 7) {
            int q = s - 1;
            lo = W1[(l * CIN + q) * CIN + c0];
            hi = ok1 ? W1[(l * CIN + q) * CIN + c1] : 0.f;
        } else if (s < 14) {
            int row = 6 + (s - 7);
            lo = W1[(l * CIN + row) * CIN + c0];
            hi = ok1 ? W1[(l * CIN + row) * CIN + c1] : 0.f;
        } else {
            int d = s - 14;
            lo = W2[(l * CIN + c0) * DD + d];
            hi = ok1 ? W2[(l * CIN + c1) * DD + d] : 0.f;
        }
        gStage[t] = pk2(lo, hi);
    }
    // misc floats: [0..17]=b2, [18..35]=gw, [36..53]=gb, packed pairwise into u64
    if (threadIdx.x < MISC_N) {
        int j  = threadIdx.x;
        int f0 = 2 * j, f1 = 2 * j + 1;
        auto pick = [&](int f) -> float {
            if (f < 18)      return b2[f];
            else if (f < 36) return gw[f - 18];
            else             return gb[f - 36];
        };
        gStage[PACK_N + j] = pk2(pick(f0), f1 < 54 ? pick(f1) : 0.f);
    }
}

__global__ void __launch_bounds__(128, 7)
atom_mp_kernel(const float* __restrict__ dist, const float* __restrict__ atom,
               float* __restrict__ out, int P)
{
    int t  = blockIdx.x * blockDim.x + threadIdx.x;
    int p  = t >> 2;          // point id
    int q  = t & 3;           // lane-within-point: owns neighbors 4q..4q+3
    if (p >= P) return;
    unsigned gmask = 0xFu << (threadIdx.x & 28);

    const float* cMisc = reinterpret_cast<const float*>(cAll + PACK_N);

    // ---- load this lane's 4 neighbors, broadcast-pack (a,a) once ----
    float ar[24];
    const float4* a4 = reinterpret_cast<const float4*>(atom + (size_t)p * (KK * DD) + q * 24);
    #pragma unroll
    for (int i = 0; i < 6; i++) {
        float4 v = a4[i];
        ar[4*i+0] = v.x; ar[4*i+1] = v.y; ar[4*i+2] = v.z; ar[4*i+3] = v.w;
    }
    float4 dv = *reinterpret_cast<const float4*>(dist + (size_t)p * KK + q * 4);
    float dk[4] = {dv.x, dv.y, dv.z, dv.w};

    u64 nb[28];   // nb[k*7+i]: i=0..5 atom channel, i=6 dist; both halves equal
    #pragma unroll
    for (int k = 0; k < 4; k++) {
        #pragma unroll
        for (int i = 0; i < 6; i++)
            nb[k * 7 + i] = pk2(ar[k * 6 + i], ar[k * 6 + i]);
        nb[k * 7 + 6] = pk2(dk[k], dk[k]);
    }

    const u64 C06 = pk2(0.6f, 0.6f);
    const u64 C04 = pk2(0.4f, 0.4f);

    float pe[6] = {1.f, 1.f, 1.f, 1.f, 1.f, 1.f};

    #pragma unroll
    for (int l = 0; l < NL; l++) {
        u64 peb[6];
        #pragma unroll
        for (int i = 0; i < 6; i++) peb[i] = pk2(pe[i], pe[i]);

        u64 m2[6];

        #pragma unroll
        for (int cp = 0; cp < NCP; cp++) {
            const int o = (l * NCP + cp) * WPC;   // compile-time after unroll
            const ulonglong2* wv = reinterpret_cast<const ulonglong2*>(cAll + o);
            // vectorized constant loads (LDCU.128): group 1 = bias + pe + nbr rows
            ulonglong2 A0 = wv[0], A1 = wv[1], A2 = wv[2], A3 = wv[3];
            ulonglong2 A4 = wv[4], A5 = wv[5], A6 = wv[6];

            // base2 = (b1 + pe . W1[0:6]) for channels (c0, c1) — 2-tree dep chain
            u64 ba = fma2(peb[0], A0.y, A0.x);
            u64 bb = mul2(peb[1], A1.x);
            ba = fma2(peb[2], A1.y, ba);
            bb = fma2(peb[3], A2.x, bb);
            ba = fma2(peb[4], A2.y, ba);
            bb = fma2(peb[5], A3.x, bb);
            u64 base2 = add2(ba, bb);

            // v[k] over this lane's 4 neighbors (init via first fma)
            u64 v0 = fma2(nb[0],  A3.y, base2);
            u64 v1 = fma2(nb[7],  A3.y, base2);
            u64 v2 = fma2(nb[14], A3.y, base2);
            u64 v3 = fma2(nb[21], A3.y, base2);
            v0 = fma2(nb[1],  A4.x, v0); v1 = fma2(nb[8],  A4.x, v1);
            v2 = fma2(nb[15], A4.x, v2); v3 = fma2(nb[22], A4.x, v3);
            v0 = fma2(nb[2],  A4.y, v0); v1 = fma2(nb[9],  A4.y, v1);
            v2 = fma2(nb[16], A4.y, v2); v3 = fma2(nb[23], A4.y, v3);
            v0 = fma2(nb[3],  A5.x, v0); v1 = fma2(nb[10], A5.x, v1);
            v2 = fma2(nb[17], A5.x, v2); v3 = fma2(nb[24], A5.x, v3);
            v0 = fma2(nb[4],  A5.y, v0); v1 = fma2(nb[11], A5.y, v1);
            v2 = fma2(nb[18], A5.y, v2); v3 = fma2(nb[25], A5.y, v3);
            v0 = fma2(nb[5],  A6.x, v0); v1 = fma2(nb[12], A6.x, v1);
            v2 = fma2(nb[19], A6.x, v2); v3 = fma2(nb[26], A6.x, v3);
            v0 = fma2(nb[6],  A6.y, v0); v1 = fma2(nb[13], A6.y, v1);
            v2 = fma2(nb[20], A6.y, v2); v3 = fma2(nb[27], A6.y, v3);

            // partial sum_k lrelu(v_k) = 0.6*sum v + 0.4*sum |v|, packed (c0,c1)
            u64 sv = add2(add2(v0, v1), add2(v2, v3));
            u64 sa = add2(add2(ABS2(v0), ABS2(v1)), add2(ABS2(v2), ABS2(v3)));
            u64 hc2 = fma2(sa, C04, mul2(sv, C06));

            // group 2: W2 rows, loaded at use site (short live range)
            ulonglong2 A7 = wv[7], A8 = wv[8], A9 = wv[9];

            // msg partial: packed accumulate, both channels at once
            if (cp == 0) {
                m2[0] = mul2(hc2, A7.x); m2[1] = mul2(hc2, A7.y);
                m2[2] = mul2(hc2, A8.x); m2[3] = mul2(hc2, A8.y);
                m2[4] = mul2(hc2, A9.x); m2[5] = mul2(hc2, A9.y);
            } else {
                m2[0] = fma2(hc2, A7.x, m2[0]); m2[1] = fma2(hc2, A7.y, m2[1]);
                m2[2] = fma2(hc2, A8.x, m2[2]); m2[3] = fma2(hc2, A8.y, m2[3]);
                m2[4] = fma2(hc2, A9.x, m2[4]); m2[5] = fma2(hc2, A9.y, m2[5]);
            }
        }

        // fold packed channel halves, reduce across the 4 lanes, add 16*b2
        float msg[6];
        #pragma unroll
        for (int d = 0; d < DD; d++) {
            float2 f = upk2(m2[d]);
            float m = f.x + f.y;
            m += __shfl_xor_sync(gmask, m, 1);
            m += __shfl_xor_sync(gmask, m, 2);
            msg[d] = fmaf(16.0f, cMisc[l * DD + d], m);
        }

        // GroupNorm(2 groups of 3) + affine + lrelu + residual
        #pragma unroll
        for (int g = 0; g < 2; g++) {
            float x0 = msg[3*g], x1 = msg[3*g+1], x2 = msg[3*g+2];
            float mu = (x0 + x1 + x2) * (1.0f / 3.0f);
            float e0 = x0 - mu, e1 = x1 - mu, e2 = x2 - mu;
            float var = (e0*e0 + e1*e1 + e2*e2) * (1.0f / 3.0f);
            float rs = rsqrtf(var + 1e-5f);
            float ee[3] = {e0, e1, e2};
            #pragma unroll
            for (int u = 0; u < 3; u++) {
                int d = 3*g + u;
                float y = fmaf(ee[u] * rs, cMisc[18 + l * DD + d],
                                           cMisc[36 + l * DD + d]);
                pe[d] += 0.6f * y + 0.4f * fabsf(y);
            }
        }
    }

    // lane q writes pe[2q], pe[2q+1] (q < 3)
    float2 o;
    if (q == 0)      o = make_float2(pe[0], pe[1]);
    else if (q == 1) o = make_float2(pe[2], pe[3]);
    else             o = make_float2(pe[4], pe[5]);
    if (q < 3)
        *reinterpret_cast<float2*>(out + (size_t)p * DD + 2 * q) = o;
}

extern "C" void kernel_launch(void* const* d_in, const int* in_sizes, int n_in,
                              void* d_out, int out_size) {
    const float* dist = (const float*)d_in[0];
    const float* atom = (const float*)d_in[1];
    const float* W1   = (const float*)d_in[2];
    const float* b1   = (const float*)d_in[3];
    const float* W2   = (const float*)d_in[4];
    const float* b2   = (const float*)d_in[5];
    const float* gw   = (const float*)d_in[6];
    const float* gb   = (const float*)d_in[7];
    float* out = (float*)d_out;

    // 1) pack weights into staging (device global)
    pack_weights_kernel<<<1, 128>>>(W1, b1, W2, b2, gw, gb);

    // 2) single DtoD copy staging -> __constant__ (graph-capturable memcpy node)
    void *dstP = nullptr, *srcP = nullptr;
    cudaGetSymbolAddress(&dstP, cAll);
    cudaGetSymbolAddress(&srcP, gStage);
    cudaMemcpyAsync(dstP, srcP, sizeof(u64) * ALL_N, cudaMemcpyDeviceToDevice);

    // 3) main kernel
    int P = in_sizes[0] / KK;                 // B*N points
    long long threads = (long long)P * 4;
    int grid = (int)((threads + 127) / 128);
    atom_mp_kernel<<<grid, 128>>>(dist, atom, out, P);
}

// round 13
// speedup vs baseline: 1.0809x; 1.0809x over previous
#include <cuda_runtime.h>

#define DD   6
#define KK   16
#define CIN  13
#define NL   3
#define NCP  7        // channel pairs (14 padded channels)
#define WPC  20       // u64 weights per (layer, channel-pair)
#define PACK_N (NL * NCP * WPC)        // 420 u64
#define MISC_N 27                      // 54 floats (b2,gw,gb) as 27 u64
#define ALL_N  (PACK_N + MISC_N)

typedef unsigned long long u64;

__device__ __forceinline__ u64 pk2(float lo, float hi) {
    u64 r;
    asm("mov.b64 %0, {%1, %2};" : "=l"(r) : "f"(lo), "f"(hi));
    return r;
}
__device__ __forceinline__ float2 upk2(u64 v) {
    float2 f;
    asm("mov.b64 {%0, %1}, %2;" : "=f"(f.x), "=f"(f.y) : "l"(v));
    return f;
}
__device__ __forceinline__ u64 fma2(u64 a, u64 b, u64 c) {
    u64 r;
    asm("fma.rn.f32x2 %0, %1, %2, %3;" : "=l"(r) : "l"(a), "l"(b), "l"(c));
    return r;
}
__device__ __forceinline__ u64 add2(u64 a, u64 b) {
    u64 r;
    asm("add.rn.f32x2 %0, %1, %2;" : "=l"(r) : "l"(a), "l"(b));
    return r;
}
__device__ __forceinline__ u64 mul2(u64 a, u64 b) {
    u64 r;
    asm("mul.rn.f32x2 %0, %1, %2;" : "=l"(r) : "l"(a), "l"(b));
    return r;
}

#define ABS2(x) ((x) & 0x7FFFFFFF7FFFFFFFull)

// Packed weight row per (l, cp), 20 u64 contiguous:
//   s0      : l==0 -> precomputed base0 = (b1 + sum_q W1[q]) for (c0,c1)
//             l>0  -> (b1[c0], b1[c1])
//   s1..s6  : (W1[q][c0], W1[q][c1])        q = 0..5  (point-emb rows)
//   s7..s13 : (W1[6+i][c0], W1[6+i][c1])    i = 0..6  (neighbor rows)
//   s14..s19: 0.6*(W2[c0][d], W2[c1][d])    d = 0..5  (pre-scaled)
// c0 = 2cp, c1 = 2cp+1 (c1==13 -> zero pad)
// Appended at [PACK_N..): 54 floats = b2[18], gw[18], gb[18] as 27 u64.
__constant__ __align__(16) u64 cAll[ALL_N];

// Writes DIRECTLY into the constant bank's backing store (device pointer to
// cAll obtained host-side via cudaGetSymbolAddress). Idempotent across graph
// replays; first-use LDCU cold-misses to L2 and observes these stores.
__global__ void pack_weights_kernel(u64* __restrict__ dst,
                                    const float* __restrict__ W1, const float* __restrict__ b1,
                                    const float* __restrict__ W2, const float* __restrict__ b2,
                                    const float* __restrict__ gw, const float* __restrict__ gb)
{
    for (int t = threadIdx.x; t < PACK_N; t += blockDim.x) {
        int l  = t / (NCP * WPC);
        int r  = t % (NCP * WPC);
        int cp = r / WPC;
        int s  = r % WPC;
        int c0 = 2 * cp, c1 = 2 * cp + 1;
        bool ok1 = (c1 < CIN);
        float lo, hi;
        if (s == 0) {
            if (l == 0) {
                // precomputed base0 (pe == 1): b1[c] + sum_q W1[q][c]
                float s0 = b1[c0], s1 = ok1 ? b1[c1] : 0.f;
                for (int qq = 0; qq < 6; qq++) {
                    s0 += W1[(0 * CIN + qq) * CIN + c0];
                    if (ok1) s1 += W1[(0 * CIN + qq) * CIN + c1];
                }
                lo = s0; hi = s1;
            } else {
                lo = b1[l * CIN + c0];
                hi = ok1 ? b1[l * CIN + c1] : 0.f;
            }
        } else if (s < 7) {
            int qq = s - 1;
            lo = W1[(l * CIN + qq) * CIN + c0];
            hi = ok1 ? W1[(l * CIN + qq) * CIN + c1] : 0.f;
        } else if (s < 14) {
            int row = 6 + (s - 7);
            lo = W1[(l * CIN + row) * CIN + c0];
            hi = ok1 ? W1[(l * CIN + row) * CIN + c1] : 0.f;
        } else {
            int d = s - 14;
            lo = 0.6f * W2[(l * CIN + c0) * DD + d];
            hi = ok1 ? 0.6f * W2[(l * CIN + c1) * DD + d] : 0.f;
        }
        dst[t] = pk2(lo, hi);
    }
    // misc floats: [0..17]=b2, [18..35]=gw, [36..53]=gb, packed pairwise into u64
    if (threadIdx.x < MISC_N) {
        int j  = threadIdx.x;
        int f0 = 2 * j, f1 = 2 * j + 1;
        auto pick = [&](int f) -> float {
            if (f < 18)      return b2[f];
            else if (f < 36) return gw[f - 18];
            else             return gb[f - 36];
        };
        dst[PACK_N + j] = pk2(pick(f0), f1 < 54 ? pick(f1) : 0.f);
    }
}

__global__ void __launch_bounds__(128, 7)
atom_mp_kernel(const float* __restrict__ dist, const float* __restrict__ atom,
               float* __restrict__ out, int P)
{
    int t  = blockIdx.x * blockDim.x + threadIdx.x;
    int p  = t >> 2;          // point id
    int q  = t & 3;           // lane-within-point: owns neighbors 4q..4q+3
    if (p >= P) return;
    unsigned gmask = 0xFu << (threadIdx.x & 28);

    const float* cMisc = reinterpret_cast<const float*>(cAll + PACK_N);

    // ---- load this lane's 4 neighbors, broadcast-pack (a,a) once ----
    float ar[24];
    const float4* a4 = reinterpret_cast<const float4*>(atom + (size_t)p * (KK * DD) + q * 24);
    #pragma unroll
    for (int i = 0; i < 6; i++) {
        float4 v = a4[i];
        ar[4*i+0] = v.x; ar[4*i+1] = v.y; ar[4*i+2] = v.z; ar[4*i+3] = v.w;
    }
    float4 dv = *reinterpret_cast<const float4*>(dist + (size_t)p * KK + q * 4);
    float dk[4] = {dv.x, dv.y, dv.z, dv.w};

    u64 nb[28];   // nb[k*7+i]: i=0..5 atom channel, i=6 dist; both halves equal
    #pragma unroll
    for (int k = 0; k < 4; k++) {
        #pragma unroll
        for (int i = 0; i < 6; i++)
            nb[k * 7 + i] = pk2(ar[k * 6 + i], ar[k * 6 + i]);
        nb[k * 7 + 6] = pk2(dk[k], dk[k]);
    }

    const u64 C23 = pk2(2.0f / 3.0f, 2.0f / 3.0f);

    float pe[6] = {1.f, 1.f, 1.f, 1.f, 1.f, 1.f};

    #pragma unroll
    for (int l = 0; l < NL; l++) {
        u64 peb[6];
        if (l > 0) {
            #pragma unroll
            for (int i = 0; i < 6; i++) peb[i] = pk2(pe[i], pe[i]);
        }

        u64 m2[6];

        #pragma unroll
        for (int cp = 0; cp < NCP; cp++) {
            const int o = (l * NCP + cp) * WPC;   // compile-time after unroll
            const ulonglong2* wv = reinterpret_cast<const ulonglong2*>(cAll + o);
            ulonglong2 A0 = wv[0], A1 = wv[1], A2 = wv[2], A3 = wv[3];
            ulonglong2 A4 = wv[4], A5 = wv[5], A6 = wv[6];

            // base2 for channels (c0,c1): layer 0 is fully precomputed in s0
            u64 base2;
            if (l == 0) {
                base2 = A0.x;
            } else {
                u64 ba = fma2(peb[0], A0.y, A0.x);
                u64 bb = mul2(peb[1], A1.x);
                ba = fma2(peb[2], A1.y, ba);
                bb = fma2(peb[3], A2.x, bb);
                ba = fma2(peb[4], A2.y, ba);
                bb = fma2(peb[5], A3.x, bb);
                base2 = add2(ba, bb);
            }

            // v[k] over this lane's 4 neighbors (init via first fma)
            u64 v0 = fma2(nb[0],  A3.y, base2);
            u64 v1 = fma2(nb[7],  A3.y, base2);
            u64 v2 = fma2(nb[14], A3.y, base2);
            u64 v3 = fma2(nb[21], A3.y, base2);
            v0 = fma2(nb[1],  A4.x, v0); v1 = fma2(nb[8],  A4.x, v1);
            v2 = fma2(nb[15], A4.x, v2); v3 = fma2(nb[22], A4.x, v3);
            v0 = fma2(nb[2],  A4.y, v0); v1 = fma2(nb[9],  A4.y, v1);
            v2 = fma2(nb[16], A4.y, v2); v3 = fma2(nb[23], A4.y, v3);
            v0 = fma2(nb[3],  A5.x, v0); v1 = fma2(nb[10], A5.x, v1);
            v2 = fma2(nb[17], A5.x, v2); v3 = fma2(nb[24], A5.x, v3);
            v0 = fma2(nb[4],  A5.y, v0); v1 = fma2(nb[11], A5.y, v1);
            v2 = fma2(nb[18], A5.y, v2); v3 = fma2(nb[25], A5.y, v3);
            v0 = fma2(nb[5],  A6.x, v0); v1 = fma2(nb[12], A6.x, v1);
            v2 = fma2(nb[19], A6.x, v2); v3 = fma2(nb[26], A6.x, v3);
            v0 = fma2(nb[6],  A6.y, v0); v1 = fma2(nb[13], A6.y, v1);
            v2 = fma2(nb[20], A6.y, v2); v3 = fma2(nb[27], A6.y, v3);

            // partial sum_k lrelu(v_k): hc' = sv + (2/3)*sa   (0.6 folded into W2')
            u64 sv = add2(add2(v0, v1), add2(v2, v3));
            u64 sa = add2(add2(ABS2(v0), ABS2(v1)), add2(ABS2(v2), ABS2(v3)));
            u64 hc2 = fma2(sa, C23, sv);

            ulonglong2 A7 = wv[7], A8 = wv[8], A9 = wv[9];   // W2' rows

            if (cp == 0) {
                m2[0] = mul2(hc2, A7.x); m2[1] = mul2(hc2, A7.y);
                m2[2] = mul2(hc2, A8.x); m2[3] = mul2(hc2, A8.y);
                m2[4] = mul2(hc2, A9.x); m2[5] = mul2(hc2, A9.y);
            } else {
                m2[0] = fma2(hc2, A7.x, m2[0]); m2[1] = fma2(hc2, A7.y, m2[1]);
                m2[2] = fma2(hc2, A8.x, m2[2]); m2[3] = fma2(hc2, A8.y, m2[3]);
                m2[4] = fma2(hc2, A9.x, m2[4]); m2[5] = fma2(hc2, A9.y, m2[5]);
            }
        }

        // fold packed channel halves, reduce across the 4 lanes, add 16*b2
        float msg[6];
        #pragma unroll
        for (int d = 0; d < DD; d++) {
            float2 f = upk2(m2[d]);
            float m = f.x + f.y;
            m += __shfl_xor_sync(gmask, m, 1);
            m += __shfl_xor_sync(gmask, m, 2);
            msg[d] = fmaf(16.0f, cMisc[l * DD + d], m);
        }

        // GroupNorm(2 groups of 3) + affine + lrelu + residual
        #pragma unroll
        for (int g = 0; g < 2; g++) {
            float x0 = msg[3*g], x1 = msg[3*g+1], x2 = msg[3*g+2];
            float mu = (x0 + x1 + x2) * (1.0f / 3.0f);
            float e0 = x0 - mu, e1 = x1 - mu, e2 = x2 - mu;
            float var = (e0*e0 + e1*e1 + e2*e2) * (1.0f / 3.0f);
            float rs = rsqrtf(var + 1e-5f);
            float ee[3] = {e0, e1, e2};
            #pragma unroll
            for (int u = 0; u < 3; u++) {
                int d = 3*g + u;
                float y = fmaf(ee[u] * rs, cMisc[18 + l * DD + d],
                                           cMisc[36 + l * DD + d]);
                pe[d] += 0.6f * y + 0.4f * fabsf(y);
            }
        }
    }

    // lane q writes pe[2q], pe[2q+1] (q < 3)
    float2 o;
    if (q == 0)      o = make_float2(pe[0], pe[1]);
    else if (q == 1) o = make_float2(pe[2], pe[3]);
    else             o = make_float2(pe[4], pe[5]);
    if (q < 3)
        *reinterpret_cast<float2*>(out + (size_t)p * DD + 2 * q) = o;
}

extern "C" void kernel_launch(void* const* d_in, const int* in_sizes, int n_in,
                              void* d_out, int out_size) {
    const float* dist = (const float*)d_in[0];
    const float* atom = (const float*)d_in[1];
    const float* W1   = (const float*)d_in[2];
    const float* b1   = (const float*)d_in[3];
    const float* W2   = (const float*)d_in[4];
    const float* b2   = (const float*)d_in[5];
    const float* gw   = (const float*)d_in[6];
    const float* gb   = (const float*)d_in[7];
    float* out = (float*)d_out;

    // pack weights straight into the constant bank's backing store
    void* dstC = nullptr;
    cudaGetSymbolAddress(&dstC, cAll);
    pack_weights_kernel<<<1, 128>>>((u64*)dstC, W1, b1, W2, b2, gw, gb);

    int P = in_sizes[0] / KK;                 // B*N points
    long long threads = (long long)P * 4;
    int grid = (int)((threads + 127) / 128);
    atom_mp_kernel<<<grid, 128>>>(dist, atom, out, P);
}